// round 1
// baseline (speedup 1.0000x reference)
#include <cuda_runtime.h>

#define Bb  4
#define Ss  2048
#define Dd  1024
#define Hh  16
#define DHd 64
#define Mm  (Bb*Ss)   // 8192

// Scratch (device globals: no runtime allocation allowed)
__device__ float g_q[(size_t)Mm*Dd];
__device__ float g_k[(size_t)Mm*Dd];
__device__ float g_v[(size_t)Mm*Dd];
__device__ float g_ctx[(size_t)Mm*Dd];

// ---------------------------------------------------------------------------
// GEMM: out = X @ W^T + bias (+ resid). X:[M,1024] row-major, W:[1024,1024] row-major.
// 128x128 tile, BK=8, 256 threads, 8x8 per thread.
// MODE 0: store to head-split (B,H,S,64) layout. MODE 1: row-major + residual.
// ---------------------------------------------------------------------------
template<int MODE>
__global__ void __launch_bounds__(256, 2)
gemm128(const float* __restrict__ X, const float* __restrict__ W,
        const float* __restrict__ bias, const float* __restrict__ resid,
        float* __restrict__ out)
{
    __shared__ __align__(16) float As[8][128];
    __shared__ __align__(16) float Bs[8][128];
    const int tid = threadIdx.x;
    const int tx = tid & 15, ty = tid >> 4;
    const int m0 = blockIdx.y << 7, n0 = blockIdx.x << 7;
    const int lr = tid >> 1;
    const int lc = (tid & 1) << 2;
    const float* Ap = X + (size_t)(m0 + lr) * Dd + lc;
    const float* Bp = W + (size_t)(n0 + lr) * Dd + lc;

    float acc[8][8];
#pragma unroll
    for (int i = 0; i < 8; i++)
#pragma unroll
        for (int j = 0; j < 8; j++) acc[i][j] = 0.f;

    for (int k0 = 0; k0 < Dd; k0 += 8) {
        const float4 a = *(const float4*)(Ap + k0);
        const float4 b = *(const float4*)(Bp + k0);
        __syncthreads();
        As[lc+0][lr] = a.x; As[lc+1][lr] = a.y; As[lc+2][lr] = a.z; As[lc+3][lr] = a.w;
        Bs[lc+0][lr] = b.x; Bs[lc+1][lr] = b.y; Bs[lc+2][lr] = b.z; Bs[lc+3][lr] = b.w;
        __syncthreads();
#pragma unroll
        for (int kk = 0; kk < 8; kk++) {
            float ra[8], rb[8];
            *(float4*)&ra[0] = *(const float4*)&As[kk][ty*8];
            *(float4*)&ra[4] = *(const float4*)&As[kk][ty*8+4];
            *(float4*)&rb[0] = *(const float4*)&Bs[kk][tx*8];
            *(float4*)&rb[4] = *(const float4*)&Bs[kk][tx*8+4];
#pragma unroll
            for (int i = 0; i < 8; i++)
#pragma unroll
                for (int j = 0; j < 8; j++)
                    acc[i][j] += ra[i]*rb[j];
        }
    }

#pragma unroll
    for (int i = 0; i < 8; i++) {
        const int m = m0 + ty*8 + i;
        if (MODE == 0) {
            const int bidx = m >> 11, s = m & (Ss-1);
#pragma unroll
            for (int j = 0; j < 8; j++) {
                const int n = n0 + tx*8 + j;
                const int h = n >> 6, d = n & 63;
                out[(((size_t)(bidx*Hh + h))*Ss + s)*DHd + d] = acc[i][j] + bias[n];
            }
        } else {
            const size_t base = (size_t)m*Dd + n0 + tx*8;
#pragma unroll
            for (int j = 0; j < 8; j++) {
                const int n = n0 + tx*8 + j;
                out[base + j] = acc[i][j] + bias[n] + resid[base + j];
            }
        }
    }
}

// ---------------------------------------------------------------------------
// Flash attention: per (b,h), 64 query rows per block, streaming K/V tiles of 64.
// 256 threads (16x16), each owns a 4x4 tile. Online softmax, P^T stored with
// XOR swizzle so both S=QK^T and O=PV run at 2 LDS.128 per 16 FFMA.
// Writes ctx in merged (B,S,D) layout for the output projection GEMM.
// ---------------------------------------------------------------------------
__global__ void __launch_bounds__(256)
attn64(const int* __restrict__ mask)
{
    extern __shared__ __align__(16) float sm[];
    float* Qst = sm;             // [64 d][64 q]
    float* Kst = sm + 4096;      // [64 d][64 kpos]
    float* Vs  = sm + 8192;      // [64 kpos][64 d]
    float* Pst = sm + 12288;     // [64 kpos][64 q] (swizzled)
    int*   msk = (int*)(sm + 16384);

    const int tid = threadIdx.x;
    const int tx = tid & 15, ty = tid >> 4;
    const int tx4 = tx << 2, ty4 = ty << 2;
    const int bh = blockIdx.y;
    const int b  = bh >> 4;
    const int h  = bh & 15;
    const int q0 = blockIdx.x << 6;
    const float* Qh = g_q + (size_t)bh * Ss * DHd;
    const float* Kh = g_k + (size_t)bh * Ss * DHd;
    const float* Vh = g_v + (size_t)bh * Ss * DHd;
    const int* mrow = mask + b * Ss;

    const int lc  = tid & 63;
    const int ld0 = (tid >> 6) << 4;

    // Load Q tile transposed: Qst[d][q]
    {
        const float* src = Qh + (size_t)(q0 + lc) * DHd + ld0;
        const float4 v0 = *(const float4*)(src + 0);
        const float4 v1 = *(const float4*)(src + 4);
        const float4 v2 = *(const float4*)(src + 8);
        const float4 v3 = *(const float4*)(src + 12);
        const float tmp[16] = {v0.x,v0.y,v0.z,v0.w, v1.x,v1.y,v1.z,v1.w,
                               v2.x,v2.y,v2.z,v2.w, v3.x,v3.y,v3.z,v3.w};
#pragma unroll
        for (int i = 0; i < 16; i++) Qst[(ld0+i)*64 + lc] = tmp[i];
    }

    float acc[4][4];
    float mI[4], lI[4];
#pragma unroll
    for (int i = 0; i < 4; i++) {
        mI[i] = -1e30f; lI[i] = 0.f;
#pragma unroll
        for (int j = 0; j < 4; j++) acc[i][j] = 0.f;
    }

    for (int k0 = 0; k0 < Ss; k0 += 64) {
        __syncthreads();   // prior PV (reads Pst/Vs) done before overwriting tiles
        {
            const float* src = Kh + (size_t)(k0 + lc) * DHd + ld0;
            const float4 v0 = *(const float4*)(src + 0);
            const float4 v1 = *(const float4*)(src + 4);
            const float4 v2 = *(const float4*)(src + 8);
            const float4 v3 = *(const float4*)(src + 12);
            const float tmp[16] = {v0.x,v0.y,v0.z,v0.w, v1.x,v1.y,v1.z,v1.w,
                                   v2.x,v2.y,v2.z,v2.w, v3.x,v3.y,v3.z,v3.w};
#pragma unroll
            for (int i = 0; i < 16; i++) Kst[(ld0+i)*64 + lc] = tmp[i];
        }
        {
            float4* dv = (float4*)Vs;
            const float4* sv = (const float4*)(Vh + (size_t)k0 * DHd);
#pragma unroll
            for (int f = 0; f < 4; f++) dv[tid + 256*f] = sv[tid + 256*f];
        }
        if (tid < 64) msk[tid] = mrow[k0 + tid];
        __syncthreads();

        // S = Q K^T (4x4 per thread)
        float s[4][4];
#pragma unroll
        for (int i = 0; i < 4; i++)
#pragma unroll
            for (int j = 0; j < 4; j++) s[i][j] = 0.f;
#pragma unroll 8
        for (int kk = 0; kk < 64; kk++) {
            const float4 qa = *(const float4*)&Qst[kk*64 + ty4];
            const float4 kb = *(const float4*)&Kst[kk*64 + tx4];
            const float qv[4] = {qa.x, qa.y, qa.z, qa.w};
            const float kv[4] = {kb.x, kb.y, kb.z, kb.w};
#pragma unroll
            for (int i = 0; i < 4; i++)
#pragma unroll
                for (int j = 0; j < 4; j++)
                    s[i][j] += qv[i]*kv[j];
        }

        // scale + mask (reference: scale, then replace masked with -1e9)
#pragma unroll
        for (int j = 0; j < 4; j++) {
            const int mv = msk[tx4 + j];
#pragma unroll
            for (int i = 0; i < 4; i++)
                s[i][j] = mv ? s[i][j]*0.125f : -1e9f;
        }

        // online softmax (rows shared by the 16 threads of one ty group = half warp)
#pragma unroll
        for (int i = 0; i < 4; i++) {
            float mx = fmaxf(fmaxf(s[i][0], s[i][1]), fmaxf(s[i][2], s[i][3]));
#pragma unroll
            for (int off = 8; off >= 1; off >>= 1)
                mx = fmaxf(mx, __shfl_xor_sync(0xffffffffu, mx, off, 16));
            const float mnew = fmaxf(mI[i], mx);
            const float al = exp2f((mI[i] - mnew) * 1.44269504f);
            mI[i] = mnew;
            float rs = 0.f;
#pragma unroll
            for (int j = 0; j < 4; j++) {
                const float pv = exp2f((s[i][j] - mnew) * 1.44269504f);
                s[i][j] = pv;
                rs += pv;
            }
#pragma unroll
            for (int off = 8; off >= 1; off >>= 1)
                rs += __shfl_xor_sync(0xffffffffu, rs, off, 16);
            lI[i] = lI[i]*al + rs;
#pragma unroll
            for (int j = 0; j < 4; j++) acc[i][j] *= al;
        }

        // store P transposed (swizzled rows to break the stride-64 bank pattern)
#pragma unroll
        for (int jj = 0; jj < 4; jj++) {
            const int c = tx4 + jj;
            *(float4*)&Pst[c*64 + (ty4 ^ ((c & 15) << 2))] =
                make_float4(s[0][jj], s[1][jj], s[2][jj], s[3][jj]);
        }
        __syncthreads();

        // O += P V
#pragma unroll 8
        for (int c = 0; c < 64; c++) {
            const float4 pa = *(const float4*)&Pst[c*64 + (ty4 ^ ((c & 15) << 2))];
            const float4 vb = *(const float4*)&Vs[c*64 + tx4];
            const float pv[4] = {pa.x, pa.y, pa.z, pa.w};
            const float vv[4] = {vb.x, vb.y, vb.z, vb.w};
#pragma unroll
            for (int i = 0; i < 4; i++)
#pragma unroll
                for (int j = 0; j < 4; j++)
                    acc[i][j] += pv[i]*vv[j];
        }
    }

    // write ctx in merged (B,S,D) layout
#pragma unroll
    for (int i = 0; i < 4; i++) {
        const float inv = 1.f / lI[i];
        const size_t o = ((size_t)b*Ss + q0 + ty4 + i) * Dd + h*DHd + tx4;
        *(float4*)&g_ctx[o] = make_float4(acc[i][0]*inv, acc[i][1]*inv,
                                          acc[i][2]*inv, acc[i][3]*inv);
    }
}

// ---------------------------------------------------------------------------
// LayerNorm: one block per row of 1024, in-place on d_out.
// ---------------------------------------------------------------------------
__global__ void __launch_bounds__(256)
ln1024(float* __restrict__ x, const float* __restrict__ gamma, const float* __restrict__ beta)
{
    __shared__ float red[16];
    const int row = blockIdx.x, t = threadIdx.x;
    float* xr = x + (size_t)row * Dd;
    const float4 v = *(const float4*)(xr + t*4);
    float s  = v.x + v.y + v.z + v.w;
    float s2 = v.x*v.x + v.y*v.y + v.z*v.z + v.w*v.w;
#pragma unroll
    for (int off = 16; off >= 1; off >>= 1) {
        s  += __shfl_xor_sync(0xffffffffu, s,  off);
        s2 += __shfl_xor_sync(0xffffffffu, s2, off);
    }
    if ((t & 31) == 0) { red[t>>5] = s; red[8 + (t>>5)] = s2; }
    __syncthreads();
    if (t == 0) {
        float a = 0.f, c = 0.f;
#pragma unroll
        for (int w = 0; w < 8; w++) { a += red[w]; c += red[8+w]; }
        red[0] = a; red[8] = c;
    }
    __syncthreads();
    const float mean = red[0] * (1.f/Dd);
    const float var  = red[8] * (1.f/Dd) - mean*mean;
    const float rstd = rsqrtf(var + 1e-5f);
    const float4 g  = *(const float4*)(gamma + t*4);
    const float4 be = *(const float4*)(beta  + t*4);
    float4 o;
    o.x = (v.x - mean)*rstd*g.x + be.x;
    o.y = (v.y - mean)*rstd*g.y + be.y;
    o.z = (v.z - mean)*rstd*g.z + be.z;
    o.w = (v.w - mean)*rstd*g.w + be.w;
    *(float4*)(xr + t*4) = o;
}

// ---------------------------------------------------------------------------
extern "C" void kernel_launch(void* const* d_in, const int* in_sizes, int n_in,
                              void* d_out, int out_size)
{
    const float* Q    = (const float*)d_in[0];
    const float* K    = (const float*)d_in[1];
    const float* V    = (const float*)d_in[2];
    const int*   mask = (const int*)  d_in[3];
    const float* Wq   = (const float*)d_in[4];
    const float* bq   = (const float*)d_in[5];
    const float* Wk   = (const float*)d_in[6];
    const float* bk   = (const float*)d_in[7];
    const float* Wv   = (const float*)d_in[8];
    const float* bv   = (const float*)d_in[9];
    const float* Wo   = (const float*)d_in[10];
    const float* bo   = (const float*)d_in[11];
    const float* gam  = (const float*)d_in[12];
    const float* bet  = (const float*)d_in[13];
    float* out = (float*)d_out;

    float *gq, *gk, *gv, *gctx;
    cudaGetSymbolAddress((void**)&gq,   g_q);
    cudaGetSymbolAddress((void**)&gk,   g_k);
    cudaGetSymbolAddress((void**)&gv,   g_v);
    cudaGetSymbolAddress((void**)&gctx, g_ctx);

    const dim3 gg(Dd/128, Mm/128);   // (8, 64)
    gemm128<0><<<gg, 256>>>(Q, Wq, bq, nullptr, gq);
    gemm128<0><<<gg, 256>>>(K, Wk, bk, nullptr, gk);
    gemm128<0><<<gg, 256>>>(V, Wv, bv, nullptr, gv);

    const int smem = (16384 + 64) * 4;   // 65,792 B
    cudaFuncSetAttribute(attn64, cudaFuncAttributeMaxDynamicSharedMemorySize, smem);
    attn64<<<dim3(Ss/64, Bb*Hh), 256, smem>>>(mask);

    gemm128<1><<<gg, 256>>>(gctx, Wo, bo, Q, out);
    ln1024<<<Mm, 256>>>(out, gam, bet);
}

// round 5
// speedup vs baseline: 1.4410x; 1.4410x over previous
#include <cuda_runtime.h>
#include <cuda_bf16.h>
#include <cstdint>

#define Bb  4
#define Ss  2048
#define Dd  1024
#define Hh  16
#define DHd 64
#define Mm  (Bb*Ss)   // 8192

// ---------------- scratch (device globals; no runtime alloc) ----------------
__device__ float g_q[(size_t)Mm*Dd];
__device__ float g_k[(size_t)Mm*Dd];
__device__ float g_v[(size_t)Mm*Dd];
__device__ float g_ctx[(size_t)Mm*Dd];
__device__ __nv_bfloat16 g_xh[(size_t)Mm*Dd];
__device__ __nv_bfloat16 g_xl[(size_t)Mm*Dd];
__device__ __nv_bfloat16 g_wh[(size_t)4*Dd*Dd];
__device__ __nv_bfloat16 g_wl[(size_t)4*Dd*Dd];

// ---------------- helpers ----------------
__device__ __forceinline__ uint32_t smem_u32(const void* p) {
    uint32_t a;
    asm("{ .reg .u64 t; cvta.to.shared.u64 t, %1; cvt.u32.u64 %0, t; }" : "=r"(a) : "l"(p));
    return a;
}
__device__ __forceinline__ void cpa16(uint32_t dst, const void* src) {
    asm volatile("cp.async.cg.shared.global [%0], [%1], 16;" :: "r"(dst), "l"(src));
}
#define CP_COMMIT() asm volatile("cp.async.commit_group;" ::: "memory")
#define CP_WAIT(n)  asm volatile("cp.async.wait_group %0;" :: "n"(n) : "memory")

__device__ __forceinline__ void ldm4(uint32_t* d, uint32_t addr) {
    asm volatile("ldmatrix.sync.aligned.m8n8.x4.shared.b16 {%0,%1,%2,%3}, [%4];"
        : "=r"(d[0]), "=r"(d[1]), "=r"(d[2]), "=r"(d[3]) : "r"(addr));
}
__device__ __forceinline__ void mma16816(float* c, const uint32_t* a, const uint32_t* b) {
    asm volatile(
        "mma.sync.aligned.m16n8k16.row.col.f32.bf16.bf16.f32 "
        "{%0,%1,%2,%3}, {%4,%5,%6,%7}, {%8,%9}, {%0,%1,%2,%3};"
        : "+f"(c[0]), "+f"(c[1]), "+f"(c[2]), "+f"(c[3])
        : "r"(a[0]), "r"(a[1]), "r"(a[2]), "r"(a[3]), "r"(b[0]), "r"(b[1]));
}

// ---------------------------------------------------------------------------
// fp32 -> bf16 hi/lo split
// ---------------------------------------------------------------------------
__global__ void __launch_bounds__(256)
cvt_split(const float* __restrict__ x, __nv_bfloat16* __restrict__ hi,
          __nv_bfloat16* __restrict__ lo, int n4)
{
    const int i = blockIdx.x * 256 + threadIdx.x;
    if (i >= n4) return;
    const float4 v = ((const float4*)x)[i];
    __nv_bfloat16 h0 = __float2bfloat16(v.x);
    __nv_bfloat16 h1 = __float2bfloat16(v.y);
    __nv_bfloat16 h2 = __float2bfloat16(v.z);
    __nv_bfloat16 h3 = __float2bfloat16(v.w);
    __nv_bfloat16 l0 = __float2bfloat16(v.x - __bfloat162float(h0));
    __nv_bfloat16 l1 = __float2bfloat16(v.y - __bfloat162float(h1));
    __nv_bfloat16 l2 = __float2bfloat16(v.z - __bfloat162float(h2));
    __nv_bfloat16 l3 = __float2bfloat16(v.w - __bfloat162float(h3));
    ((__nv_bfloat162*)hi)[2*i]   = __nv_bfloat162(h0, h1);
    ((__nv_bfloat162*)hi)[2*i+1] = __nv_bfloat162(h2, h3);
    ((__nv_bfloat162*)lo)[2*i]   = __nv_bfloat162(l0, l1);
    ((__nv_bfloat162*)lo)[2*i+1] = __nv_bfloat162(l2, l3);
}

// ---------------------------------------------------------------------------
// Split-bf16 GEMM via mma.sync: out[M,N] = X @ W^T (+bias [+resid])
// 128x128 tile, BK=64, 3-stage cp.async pipeline, 8 warps (4x2), warp=32x64.
// MODE 0: head-split store (B,H,S,64). MODE 1: row-major +bias+resid.
// ---------------------------------------------------------------------------
#define NIT 16
#define STG_B 65536       // per stage: Ah,Al,Bh,Bl each 128x64 bf16 = 16KB
#define GSMEM (3*STG_B)   // 196,608 B

template<int MODE>
__global__ void __launch_bounds__(256, 1)
mmagemm(const __nv_bfloat16* __restrict__ xh, const __nv_bfloat16* __restrict__ xl,
        const __nv_bfloat16* __restrict__ wh, const __nv_bfloat16* __restrict__ wl,
        const float* __restrict__ bias, const float* __restrict__ resid,
        float* __restrict__ out)
{
    extern __shared__ __align__(128) char smem[];
    const uint32_t sb = smem_u32(smem);
    const int tid = threadIdx.x;
    const int wid = tid >> 5, lane = tid & 31;
    const int m0 = blockIdx.y << 7, n0 = blockIdx.x << 7;
    const int m0w = (wid & 3) * 32;          // warp row offset in tile
    const int n0w = (wid >> 2) * 64;         // warp col offset in tile

    // cp.async slice: thread -> row r=tid>>1, 4 consecutive 16B chunks
    const int r  = tid >> 1;
    const int c0 = (tid & 1) * 4;
    const __nv_bfloat16* Axh = xh + (size_t)(m0 + r) * Dd;
    const __nv_bfloat16* Axl = xl + (size_t)(m0 + r) * Dd;
    const __nv_bfloat16* Bwh = wh + (size_t)(n0 + r) * Dd;
    const __nv_bfloat16* Bwl = wl + (size_t)(n0 + r) * Dd;

    auto load_stage = [&](int it) {
        const int k0 = it << 6;
        const uint32_t st = sb + (it % 3) * STG_B;
#pragma unroll
        for (int c = 0; c < 4; c++) {
            const int ch = c0 + c;
            const uint32_t sw = (uint32_t)(r * 128 + ((ch ^ (r & 7)) << 4));
            const int ke = k0 + ch * 8;
            cpa16(st + sw,              Axh + ke);
            cpa16(st + 16384 + sw,      Axl + ke);
            cpa16(st + 32768 + sw,      Bwh + ke);
            cpa16(st + 49152 + sw,      Bwl + ke);
        }
        CP_COMMIT();
    };

    float acc[2][8][4];
#pragma unroll
    for (int i = 0; i < 2; i++)
#pragma unroll
        for (int j = 0; j < 8; j++)
#pragma unroll
            for (int k = 0; k < 4; k++) acc[i][j][k] = 0.f;

    load_stage(0);
    load_stage(1);

    const int grp = lane >> 3, lr = lane & 7;

    for (int it = 0; it < NIT; it++) {
        if (it == NIT - 1) { CP_WAIT(0); } else { CP_WAIT(1); }
        __syncthreads();
        const uint32_t sA = sb + (it % 3) * STG_B;

#pragma unroll
        for (int ks = 0; ks < 4; ks++) {
            uint32_t ah[2][4], al[2][4], bh[4][4], bl[4][4];
#pragma unroll
            for (int mt = 0; mt < 2; mt++) {
                const int arow = m0w + mt * 16 + (grp & 1) * 8 + lr;
                const int ach  = ks * 2 + (grp >> 1);
                const uint32_t ad = sA + arow * 128 + ((ach ^ (arow & 7)) << 4);
                ldm4(ah[mt], ad);
                ldm4(al[mt], ad + 16384);
            }
#pragma unroll
            for (int np = 0; np < 4; np++) {
                const int brow = n0w + np * 16 + (grp >> 1) * 8 + lr;
                const int bch  = ks * 2 + (grp & 1);
                const uint32_t bd = sA + 32768 + brow * 128 + ((bch ^ (brow & 7)) << 4);
                ldm4(bh[np], bd);
                ldm4(bl[np], bd + 16384);
            }
#pragma unroll
            for (int mt = 0; mt < 2; mt++)
#pragma unroll
                for (int np = 0; np < 4; np++)
#pragma unroll
                    for (int hf = 0; hf < 2; hf++) {
                        const int nt = np * 2 + hf;
                        mma16816(acc[mt][nt], ah[mt], &bh[np][hf * 2]);
                        mma16816(acc[mt][nt], ah[mt], &bl[np][hf * 2]);
                        mma16816(acc[mt][nt], al[mt], &bh[np][hf * 2]);
                    }
        }
        if (it + 2 < NIT) load_stage(it + 2);
    }

    // Epilogue: thread t holds rows g, g+8; cols 2*(t&3) + {0,1} per 8-wide ntile
    const int g = lane >> 2, qp = lane & 3;
#pragma unroll
    for (int mt = 0; mt < 2; mt++) {
#pragma unroll
        for (int nt = 0; nt < 8; nt++) {
            const int nb = n0 + n0w + nt * 8 + qp * 2;
            const float2 bb = *(const float2*)(bias + nb);
#pragma unroll
            for (int hr = 0; hr < 2; hr++) {
                const int m = m0 + m0w + mt * 16 + g + hr * 8;
                const float v0 = acc[mt][nt][hr * 2]     + bb.x;
                const float v1 = acc[mt][nt][hr * 2 + 1] + bb.y;
                if (MODE == 0) {
                    const int bidx = m >> 11, s = m & (Ss - 1);
                    const int h = nb >> 6, d = nb & 63;
                    float* dst = out + (((size_t)(bidx * Hh + h)) * Ss + s) * DHd + d;
                    *(float2*)dst = make_float2(v0, v1);
                } else {
                    const size_t base = (size_t)m * Dd + nb;
                    const float2 rs = *(const float2*)(resid + base);
                    *(float2*)(out + base) = make_float2(v0 + rs.x, v1 + rs.y);
                }
            }
        }
    }
}

// ---------------------------------------------------------------------------
// Flash attention (fp32, unchanged — next-round target)
// ---------------------------------------------------------------------------
__global__ void __launch_bounds__(256)
attn64(const int* __restrict__ mask)
{
    extern __shared__ __align__(16) float sm[];
    float* Qst = sm;             // [64 d][64 q]
    float* Kst = sm + 4096;      // [64 d][64 kpos]
    float* Vs  = sm + 8192;      // [64 kpos][64 d]
    float* Pst = sm + 12288;     // [64 kpos][64 q] (swizzled)
    int*   msk = (int*)(sm + 16384);

    const int tid = threadIdx.x;
    const int tx = tid & 15, ty = tid >> 4;
    const int tx4 = tx << 2, ty4 = ty << 2;
    const int bh = blockIdx.y;
    const int b  = bh >> 4;
    const int h  = bh & 15;
    const int q0 = blockIdx.x << 6;
    const float* Qh = g_q + (size_t)bh * Ss * DHd;
    const float* Kh = g_k + (size_t)bh * Ss * DHd;
    const float* Vh = g_v + (size_t)bh * Ss * DHd;
    const int* mrow = mask + b * Ss;

    const int lc  = tid & 63;
    const int ld0 = (tid >> 6) << 4;

    {
        const float* src = Qh + (size_t)(q0 + lc) * DHd + ld0;
        const float4 v0 = *(const float4*)(src + 0);
        const float4 v1 = *(const float4*)(src + 4);
        const float4 v2 = *(const float4*)(src + 8);
        const float4 v3 = *(const float4*)(src + 12);
        const float tmp[16] = {v0.x,v0.y,v0.z,v0.w, v1.x,v1.y,v1.z,v1.w,
                               v2.x,v2.y,v2.z,v2.w, v3.x,v3.y,v3.z,v3.w};
#pragma unroll
        for (int i = 0; i < 16; i++) Qst[(ld0+i)*64 + lc] = tmp[i];
    }

    float acc[4][4];
    float mI[4], lI[4];
#pragma unroll
    for (int i = 0; i < 4; i++) {
        mI[i] = -1e30f; lI[i] = 0.f;
#pragma unroll
        for (int j = 0; j < 4; j++) acc[i][j] = 0.f;
    }

    for (int k0 = 0; k0 < Ss; k0 += 64) {
        __syncthreads();
        {
            const float* src = Kh + (size_t)(k0 + lc) * DHd + ld0;
            const float4 v0 = *(const float4*)(src + 0);
            const float4 v1 = *(const float4*)(src + 4);
            const float4 v2 = *(const float4*)(src + 8);
            const float4 v3 = *(const float4*)(src + 12);
            const float tmp[16] = {v0.x,v0.y,v0.z,v0.w, v1.x,v1.y,v1.z,v1.w,
                                   v2.x,v2.y,v2.z,v2.w, v3.x,v3.y,v3.z,v3.w};
#pragma unroll
            for (int i = 0; i < 16; i++) Kst[(ld0+i)*64 + lc] = tmp[i];
        }
        {
            float4* dv = (float4*)Vs;
            const float4* sv = (const float4*)(Vh + (size_t)k0 * DHd);
#pragma unroll
            for (int f = 0; f < 4; f++) dv[tid + 256*f] = sv[tid + 256*f];
        }
        if (tid < 64) msk[tid] = mrow[k0 + tid];
        __syncthreads();

        float s[4][4];
#pragma unroll
        for (int i = 0; i < 4; i++)
#pragma unroll
            for (int j = 0; j < 4; j++) s[i][j] = 0.f;
#pragma unroll 8
        for (int kk = 0; kk < 64; kk++) {
            const float4 qa = *(const float4*)&Qst[kk*64 + ty4];
            const float4 kb = *(const float4*)&Kst[kk*64 + tx4];
            const float qv[4] = {qa.x, qa.y, qa.z, qa.w};
            const float kv[4] = {kb.x, kb.y, kb.z, kb.w};
#pragma unroll
            for (int i = 0; i < 4; i++)
#pragma unroll
                for (int j = 0; j < 4; j++)
                    s[i][j] += qv[i]*kv[j];
        }

#pragma unroll
        for (int j = 0; j < 4; j++) {
            const int mv = msk[tx4 + j];
#pragma unroll
            for (int i = 0; i < 4; i++)
                s[i][j] = mv ? s[i][j]*0.125f : -1e9f;
        }

#pragma unroll
        for (int i = 0; i < 4; i++) {
            float mx = fmaxf(fmaxf(s[i][0], s[i][1]), fmaxf(s[i][2], s[i][3]));
#pragma unroll
            for (int off = 8; off >= 1; off >>= 1)
                mx = fmaxf(mx, __shfl_xor_sync(0xffffffffu, mx, off, 16));
            const float mnew = fmaxf(mI[i], mx);
            const float al = exp2f((mI[i] - mnew) * 1.44269504f);
            mI[i] = mnew;
            float rs = 0.f;
#pragma unroll
            for (int j = 0; j < 4; j++) {
                const float pv = exp2f((s[i][j] - mnew) * 1.44269504f);
                s[i][j] = pv;
                rs += pv;
            }
#pragma unroll
            for (int off = 8; off >= 1; off >>= 1)
                rs += __shfl_xor_sync(0xffffffffu, rs, off, 16);
            lI[i] = lI[i]*al + rs;
#pragma unroll
            for (int j = 0; j < 4; j++) acc[i][j] *= al;
        }

#pragma unroll
        for (int jj = 0; jj < 4; jj++) {
            const int c = tx4 + jj;
            *(float4*)&Pst[c*64 + (ty4 ^ ((c & 15) << 2))] =
                make_float4(s[0][jj], s[1][jj], s[2][jj], s[3][jj]);
        }
        __syncthreads();

#pragma unroll 8
        for (int c = 0; c < 64; c++) {
            const float4 pa = *(const float4*)&Pst[c*64 + (ty4 ^ ((c & 15) << 2))];
            const float4 vb = *(const float4*)&Vs[c*64 + tx4];
            const float pv[4] = {pa.x, pa.y, pa.z, pa.w};
            const float vv[4] = {vb.x, vb.y, vb.z, vb.w};
#pragma unroll
            for (int i = 0; i < 4; i++)
#pragma unroll
                for (int j = 0; j < 4; j++)
                    acc[i][j] += pv[i]*vv[j];
        }
    }

#pragma unroll
    for (int i = 0; i < 4; i++) {
        const float inv = 1.f / lI[i];
        const size_t o = ((size_t)b*Ss + q0 + ty4 + i) * Dd + h*DHd + tx4;
        *(float4*)&g_ctx[o] = make_float4(acc[i][0]*inv, acc[i][1]*inv,
                                          acc[i][2]*inv, acc[i][3]*inv);
    }
}

// ---------------------------------------------------------------------------
// LayerNorm
// ---------------------------------------------------------------------------
__global__ void __launch_bounds__(256)
ln1024(float* __restrict__ x, const float* __restrict__ gamma, const float* __restrict__ beta)
{
    __shared__ float red[16];
    const int row = blockIdx.x, t = threadIdx.x;
    float* xr = x + (size_t)row * Dd;
    const float4 v = *(const float4*)(xr + t*4);
    float s  = v.x + v.y + v.z + v.w;
    float s2 = v.x*v.x + v.y*v.y + v.z*v.z + v.w*v.w;
#pragma unroll
    for (int off = 16; off >= 1; off >>= 1) {
        s  += __shfl_xor_sync(0xffffffffu, s,  off);
        s2 += __shfl_xor_sync(0xffffffffu, s2, off);
    }
    if ((t & 31) == 0) { red[t>>5] = s; red[8 + (t>>5)] = s2; }
    __syncthreads();
    if (t == 0) {
        float a = 0.f, c = 0.f;
#pragma unroll
        for (int w = 0; w < 8; w++) { a += red[w]; c += red[8+w]; }
        red[0] = a; red[8] = c;
    }
    __syncthreads();
    const float mean = red[0] * (1.f/Dd);
    const float var  = red[8] * (1.f/Dd) - mean*mean;
    const float rstd = rsqrtf(var + 1e-5f);
    const float4 g  = *(const float4*)(gamma + t*4);
    const float4 be = *(const float4*)(beta  + t*4);
    float4 o;
    o.x = (v.x - mean)*rstd*g.x + be.x;
    o.y = (v.y - mean)*rstd*g.y + be.y;
    o.z = (v.z - mean)*rstd*g.z + be.z;
    o.w = (v.w - mean)*rstd*g.w + be.w;
    *(float4*)(xr + t*4) = o;
}

// ---------------------------------------------------------------------------
extern "C" void kernel_launch(void* const* d_in, const int* in_sizes, int n_in,
                              void* d_out, int out_size)
{
    const float* Q    = (const float*)d_in[0];
    const float* K    = (const float*)d_in[1];
    const float* V    = (const float*)d_in[2];
    const int*   mask = (const int*)  d_in[3];
    const float* Wq   = (const float*)d_in[4];
    const float* bq   = (const float*)d_in[5];
    const float* Wk   = (const float*)d_in[6];
    const float* bk   = (const float*)d_in[7];
    const float* Wv   = (const float*)d_in[8];
    const float* bv   = (const float*)d_in[9];
    const float* Wo   = (const float*)d_in[10];
    const float* bo   = (const float*)d_in[11];
    const float* gam  = (const float*)d_in[12];
    const float* bet  = (const float*)d_in[13];
    float* out = (float*)d_out;

    float *gq, *gk, *gv, *gctx;
    __nv_bfloat16 *xh, *xl, *wh, *wl;
    cudaGetSymbolAddress((void**)&gq,   g_q);
    cudaGetSymbolAddress((void**)&gk,   g_k);
    cudaGetSymbolAddress((void**)&gv,   g_v);
    cudaGetSymbolAddress((void**)&gctx, g_ctx);
    cudaGetSymbolAddress((void**)&xh,   g_xh);
    cudaGetSymbolAddress((void**)&xl,   g_xl);
    cudaGetSymbolAddress((void**)&wh,   g_wh);
    cudaGetSymbolAddress((void**)&wl,   g_wl);

    cudaFuncSetAttribute(mmagemm<0>, cudaFuncAttributeMaxDynamicSharedMemorySize, GSMEM);
    cudaFuncSetAttribute(mmagemm<1>, cudaFuncAttributeMaxDynamicSharedMemorySize, GSMEM);

    const int W4 = Dd*Dd/4;
    const int X4 = Mm*Dd/4;
    const size_t WN = (size_t)Dd*Dd;
    cvt_split<<<(W4+255)/256, 256>>>(Wq, wh + 0*WN, wl + 0*WN, W4);
    cvt_split<<<(W4+255)/256, 256>>>(Wk, wh + 1*WN, wl + 1*WN, W4);
    cvt_split<<<(W4+255)/256, 256>>>(Wv, wh + 2*WN, wl + 2*WN, W4);
    cvt_split<<<(W4+255)/256, 256>>>(Wo, wh + 3*WN, wl + 3*WN, W4);

    const dim3 gg(Dd/128, Mm/128);          // (8, 64)

    cvt_split<<<(X4+255)/256, 256>>>(Q, xh, xl, X4);
    mmagemm<0><<<gg, 256, GSMEM>>>(xh, xl, wh + 0*WN, wl + 0*WN, bq, nullptr, gq);
    cvt_split<<<(X4+255)/256, 256>>>(K, xh, xl, X4);
    mmagemm<0><<<gg, 256, GSMEM>>>(xh, xl, wh + 1*WN, wl + 1*WN, bk, nullptr, gk);
    cvt_split<<<(X4+255)/256, 256>>>(V, xh, xl, X4);
    mmagemm<0><<<gg, 256, GSMEM>>>(xh, xl, wh + 2*WN, wl + 2*WN, bv, nullptr, gv);

    const int asmem = (16384 + 64) * 4;
    cudaFuncSetAttribute(attn64, cudaFuncAttributeMaxDynamicSharedMemorySize, asmem);
    attn64<<<dim3(Ss/64, Bb*Hh), 256, asmem>>>(mask);

    cvt_split<<<(X4+255)/256, 256>>>(gctx, xh, xl, X4);
    mmagemm<1><<<gg, 256, GSMEM>>>(xh, xl, wh + 3*WN, wl + 3*WN, bo, Q, out);
    ln1024<<<Mm, 256>>>(out, gam, bet);
}

// round 7
// speedup vs baseline: 3.4701x; 2.4081x over previous
#include <cuda_runtime.h>
#include <cuda_bf16.h>
#include <cstdint>

#define Bb  4
#define Ss  2048
#define Dd  1024
#define Hh  16
#define DHd 64
#define Mm  (Bb*Ss)   // 8192
#define L2E 1.44269504f

// ---------------- scratch (device globals; no runtime alloc) ----------------
__device__ __nv_bfloat16 g_xh[(size_t)Mm*Dd];
__device__ __nv_bfloat16 g_xl[(size_t)Mm*Dd];
__device__ __nv_bfloat16 g_wh[(size_t)4*Dd*Dd];
__device__ __nv_bfloat16 g_wl[(size_t)4*Dd*Dd];
__device__ __nv_bfloat16 g_qh[(size_t)Mm*Dd];
__device__ __nv_bfloat16 g_ql[(size_t)Mm*Dd];
__device__ __nv_bfloat16 g_kh[(size_t)Mm*Dd];
__device__ __nv_bfloat16 g_kl[(size_t)Mm*Dd];
__device__ __nv_bfloat16 g_vh[(size_t)Mm*Dd];

// ---------------- helpers ----------------
__device__ __forceinline__ uint32_t smem_u32(const void* p) {
    uint32_t a;
    asm("{ .reg .u64 t; cvta.to.shared.u64 t, %1; cvt.u32.u64 %0, t; }" : "=r"(a) : "l"(p));
    return a;
}
__device__ __forceinline__ void cpa16(uint32_t dst, const void* src) {
    asm volatile("cp.async.cg.shared.global [%0], [%1], 16;" :: "r"(dst), "l"(src));
}
#define CP_COMMIT() asm volatile("cp.async.commit_group;" ::: "memory")
#define CP_WAIT(n)  asm volatile("cp.async.wait_group %0;" :: "n"(n) : "memory")

__device__ __forceinline__ void ldm4(uint32_t* d, uint32_t addr) {
    asm volatile("ldmatrix.sync.aligned.m8n8.x4.shared.b16 {%0,%1,%2,%3}, [%4];"
        : "=r"(d[0]), "=r"(d[1]), "=r"(d[2]), "=r"(d[3]) : "r"(addr));
}
__device__ __forceinline__ void ldm4t(uint32_t* d, uint32_t addr) {
    asm volatile("ldmatrix.sync.aligned.m8n8.x4.trans.shared.b16 {%0,%1,%2,%3}, [%4];"
        : "=r"(d[0]), "=r"(d[1]), "=r"(d[2]), "=r"(d[3]) : "r"(addr));
}
__device__ __forceinline__ void mma16816(float* c, const uint32_t* a, const uint32_t* b) {
    asm volatile(
        "mma.sync.aligned.m16n8k16.row.col.f32.bf16.bf16.f32 "
        "{%0,%1,%2,%3}, {%4,%5,%6,%7}, {%8,%9}, {%0,%1,%2,%3};"
        : "+f"(c[0]), "+f"(c[1]), "+f"(c[2]), "+f"(c[3])
        : "r"(a[0]), "r"(a[1]), "r"(a[2]), "r"(a[3]), "r"(b[0]), "r"(b[1]));
}
__device__ __forceinline__ float ex2(float x) {
    float y; asm("ex2.approx.ftz.f32 %0, %1;" : "=f"(y) : "f"(x)); return y;
}

// ---------------------------------------------------------------------------
// fp32 -> bf16 hi/lo split
// ---------------------------------------------------------------------------
__global__ void __launch_bounds__(256)
cvt_split(const float* __restrict__ x, __nv_bfloat16* __restrict__ hi,
          __nv_bfloat16* __restrict__ lo, int n4)
{
    const int i = blockIdx.x * 256 + threadIdx.x;
    if (i >= n4) return;
    const float4 v = ((const float4*)x)[i];
    __nv_bfloat16 h0 = __float2bfloat16(v.x);
    __nv_bfloat16 h1 = __float2bfloat16(v.y);
    __nv_bfloat16 h2 = __float2bfloat16(v.z);
    __nv_bfloat16 h3 = __float2bfloat16(v.w);
    __nv_bfloat16 l0 = __float2bfloat16(v.x - __bfloat162float(h0));
    __nv_bfloat16 l1 = __float2bfloat16(v.y - __bfloat162float(h1));
    __nv_bfloat16 l2 = __float2bfloat16(v.z - __bfloat162float(h2));
    __nv_bfloat16 l3 = __float2bfloat16(v.w - __bfloat162float(h3));
    ((__nv_bfloat162*)hi)[2*i]   = __nv_bfloat162(h0, h1);
    ((__nv_bfloat162*)hi)[2*i+1] = __nv_bfloat162(h2, h3);
    ((__nv_bfloat162*)lo)[2*i]   = __nv_bfloat162(l0, l1);
    ((__nv_bfloat162*)lo)[2*i+1] = __nv_bfloat162(l2, l3);
}

// ---------------------------------------------------------------------------
// Split-bf16 GEMM via mma.sync: out[M,N] = X @ W^T + bias (+resid)
// 128x128 tile, BK=64, 3-stage cp.async, 8 warps (4x2), warp=32x64.
// MODE 0: bf16 hi+lo head-split store. MODE 2: bf16 hi only head-split.
// MODE 1: fp32 row-major +bias+resid.
// ---------------------------------------------------------------------------
#define NIT 16
#define STG_B 65536
#define GSMEM (3*STG_B)

template<int MODE>
__global__ void __launch_bounds__(256, 1)
mmagemm(const __nv_bfloat16* __restrict__ xh, const __nv_bfloat16* __restrict__ xl,
        const __nv_bfloat16* __restrict__ wh, const __nv_bfloat16* __restrict__ wl,
        const float* __restrict__ bias, const float* __restrict__ resid,
        float* __restrict__ outf,
        __nv_bfloat16* __restrict__ outh, __nv_bfloat16* __restrict__ outl)
{
    extern __shared__ __align__(128) char smem[];
    const uint32_t sb = smem_u32(smem);
    const int tid = threadIdx.x;
    const int wid = tid >> 5, lane = tid & 31;
    const int m0 = blockIdx.y << 7, n0 = blockIdx.x << 7;
    const int m0w = (wid & 3) * 32;
    const int n0w = (wid >> 2) * 64;

    const int r  = tid >> 1;
    const int c0 = (tid & 1) * 4;
    const __nv_bfloat16* Axh = xh + (size_t)(m0 + r) * Dd;
    const __nv_bfloat16* Axl = xl + (size_t)(m0 + r) * Dd;
    const __nv_bfloat16* Bwh = wh + (size_t)(n0 + r) * Dd;
    const __nv_bfloat16* Bwl = wl + (size_t)(n0 + r) * Dd;

    auto load_stage = [&](int it) {
        const int k0 = it << 6;
        const uint32_t st = sb + (it % 3) * STG_B;
#pragma unroll
        for (int c = 0; c < 4; c++) {
            const int ch = c0 + c;
            const uint32_t sw = (uint32_t)(r * 128 + ((ch ^ (r & 7)) << 4));
            const int ke = k0 + ch * 8;
            cpa16(st + sw,              Axh + ke);
            cpa16(st + 16384 + sw,      Axl + ke);
            cpa16(st + 32768 + sw,      Bwh + ke);
            cpa16(st + 49152 + sw,      Bwl + ke);
        }
        CP_COMMIT();
    };

    float acc[2][8][4];
#pragma unroll
    for (int i = 0; i < 2; i++)
#pragma unroll
        for (int j = 0; j < 8; j++)
#pragma unroll
            for (int k = 0; k < 4; k++) acc[i][j][k] = 0.f;

    load_stage(0);
    load_stage(1);

    const int grp = lane >> 3, lr = lane & 7;

    for (int it = 0; it < NIT; it++) {
        if (it == NIT - 1) { CP_WAIT(0); } else { CP_WAIT(1); }
        __syncthreads();
        const uint32_t sA = sb + (it % 3) * STG_B;

#pragma unroll
        for (int ks = 0; ks < 4; ks++) {
            uint32_t ah[2][4], al[2][4], bh[4][4], bl[4][4];
#pragma unroll
            for (int mt = 0; mt < 2; mt++) {
                const int arow = m0w + mt * 16 + (grp & 1) * 8 + lr;
                const int ach  = ks * 2 + (grp >> 1);
                const uint32_t ad = sA + arow * 128 + ((ach ^ (arow & 7)) << 4);
                ldm4(ah[mt], ad);
                ldm4(al[mt], ad + 16384);
            }
#pragma unroll
            for (int np = 0; np < 4; np++) {
                const int brow = n0w + np * 16 + (grp >> 1) * 8 + lr;
                const int bch  = ks * 2 + (grp & 1);
                const uint32_t bd = sA + 32768 + brow * 128 + ((bch ^ (brow & 7)) << 4);
                ldm4(bh[np], bd);
                ldm4(bl[np], bd + 16384);
            }
#pragma unroll
            for (int mt = 0; mt < 2; mt++)
#pragma unroll
                for (int np = 0; np < 4; np++)
#pragma unroll
                    for (int hf = 0; hf < 2; hf++) {
                        const int nt = np * 2 + hf;
                        mma16816(acc[mt][nt], ah[mt], &bh[np][hf * 2]);
                        mma16816(acc[mt][nt], ah[mt], &bl[np][hf * 2]);
                        mma16816(acc[mt][nt], al[mt], &bh[np][hf * 2]);
                    }
        }
        if (it + 2 < NIT) load_stage(it + 2);
    }

    const int g = lane >> 2, qp = lane & 3;
#pragma unroll
    for (int mt = 0; mt < 2; mt++) {
#pragma unroll
        for (int nt = 0; nt < 8; nt++) {
            const int nb = n0 + n0w + nt * 8 + qp * 2;
            const float2 bb = *(const float2*)(bias + nb);
#pragma unroll
            for (int hr = 0; hr < 2; hr++) {
                const int m = m0 + m0w + mt * 16 + g + hr * 8;
                const float v0 = acc[mt][nt][hr * 2]     + bb.x;
                const float v1 = acc[mt][nt][hr * 2 + 1] + bb.y;
                if (MODE == 0 || MODE == 2) {
                    const int bidx = m >> 11, s = m & (Ss - 1);
                    const int h = nb >> 6, d = nb & 63;
                    const size_t adr = (((size_t)(bidx * Hh + h)) * Ss + s) * DHd + d;
                    __nv_bfloat16 h0 = __float2bfloat16(v0);
                    __nv_bfloat16 h1 = __float2bfloat16(v1);
                    *(__nv_bfloat162*)(outh + adr) = __nv_bfloat162(h0, h1);
                    if (MODE == 0) {
                        __nv_bfloat16 l0 = __float2bfloat16(v0 - __bfloat162float(h0));
                        __nv_bfloat16 l1 = __float2bfloat16(v1 - __bfloat162float(h1));
                        *(__nv_bfloat162*)(outl + adr) = __nv_bfloat162(l0, l1);
                    }
                } else {
                    const size_t base = (size_t)m * Dd + nb;
                    const float2 rs = *(const float2*)(resid + base);
                    *(float2*)(outf + base) = make_float2(v0 + rs.x, v1 + rs.y);
                }
            }
        }
    }
}

// ---------------------------------------------------------------------------
// Flash attention via mma.sync. 128 q-rows/CTA, 8 warps x 16 rows, K/V tiles
// of 64, 2-stage cp.async. S = qh*kh + qh*kl + ql*kh (split). P bf16 -> PV.
// Writes ctx directly as xh/xl split into merged (B,S,D) layout.
// ---------------------------------------------------------------------------
#define AQ_H 0
#define AQ_L 16384
#define AST 32768
#define ASTRIDE 24576
#define AMSK (AST + 2*ASTRIDE)      // 81920
#define ASMEM (AMSK + 512)          // 82432
#define NKT (Ss/64)                 // 32

__global__ void __launch_bounds__(256)
attn_mma(const int* __restrict__ mask,
         __nv_bfloat16* __restrict__ oxh, __nv_bfloat16* __restrict__ oxl)
{
    extern __shared__ __align__(128) char smem[];
    const uint32_t sb = smem_u32(smem);
    const int tid = threadIdx.x;
    const int wid = tid >> 5, lane = tid & 31;
    const int g = lane >> 2, qp = lane & 3;
    const int grp = lane >> 3, lr = lane & 7;
    const int bh = blockIdx.y;
    const int b = bh >> 4, h = bh & 15;
    const int q0 = blockIdx.x << 7;

    const size_t hb = (size_t)bh << 17;     // bh * 2048 * 64
    const __nv_bfloat16* qhp = g_qh + hb;
    const __nv_bfloat16* qlp = g_ql + hb;
    const __nv_bfloat16* khp = g_kh + hb;
    const __nv_bfloat16* klp = g_kl + hb;
    const __nv_bfloat16* vhp = g_vh + hb;
    const int* mrow = mask + b * Ss;

    // Q tile async load (128 rows x 64 bf16, hi+lo)
    {
        const int rq = tid >> 1;
        const int cq = (tid & 1) * 4;
        const size_t ro = (size_t)(q0 + rq) * DHd;
#pragma unroll
        for (int c = cq; c < cq + 4; c++) {
            const uint32_t sw = (uint32_t)(rq * 128 + ((c ^ (rq & 7)) << 4));
            cpa16(sb + AQ_H + sw, qhp + ro + c * 8);
            cpa16(sb + AQ_L + sw, qlp + ro + c * 8);
        }
    }

    auto load_tile = [&](int it) {
        const uint32_t st = sb + AST + (it & 1) * ASTRIDE;
        const int rr = tid >> 2;
        const int cb = (tid & 3) * 2;
        const size_t ro = (size_t)(it * 64 + rr) * DHd;
#pragma unroll
        for (int c = cb; c < cb + 2; c++) {
            const uint32_t sw = (uint32_t)(rr * 128 + ((c ^ (rr & 7)) << 4));
            cpa16(st + sw,          khp + ro + c * 8);
            cpa16(st + 8192 + sw,   klp + ro + c * 8);
            cpa16(st + 16384 + sw,  vhp + ro + c * 8);
        }
        if (tid < 16) cpa16(sb + AMSK + (it & 1) * 256 + tid * 16, mrow + it * 64 + tid * 4);
        CP_COMMIT();
    };

    load_tile(0);     // group 0 (includes Q loads above)
    load_tile(1);     // group 1

    float m2[2] = {-1e30f, -1e30f};
    float lsum[2] = {0.f, 0.f};
    float accv[8][4];
#pragma unroll
    for (int o = 0; o < 8; o++)
#pragma unroll
        for (int c = 0; c < 4; c++) accv[o][c] = 0.f;

    uint32_t qfh[4][4], qfl[4][4];

    for (int it = 0; it < NKT; it++) {
        if (it == NKT - 1) { CP_WAIT(0); } else { CP_WAIT(1); }
        __syncthreads();

        if (it == 0) {
#pragma unroll
            for (int kk = 0; kk < 4; kk++) {
                const int arow = wid * 16 + (grp & 1) * 8 + lr;
                const int ach  = kk * 2 + (grp >> 1);
                const uint32_t ad = sb + AQ_H + arow * 128 + ((ach ^ (arow & 7)) << 4);
                ldm4(qfh[kk], ad);
                ldm4(qfl[kk], ad + 16384);
            }
        }

        const uint32_t st = sb + AST + (it & 1) * ASTRIDE;

        // S = Q K^T (split, 3 terms)
        float sacc[8][4];
#pragma unroll
        for (int o = 0; o < 8; o++)
#pragma unroll
            for (int c = 0; c < 4; c++) sacc[o][c] = 0.f;

#pragma unroll
        for (int nn = 0; nn < 4; nn++) {
#pragma unroll
            for (int kk = 0; kk < 4; kk++) {
                const int brow = nn * 16 + (grp >> 1) * 8 + lr;
                const int bch  = kk * 2 + (grp & 1);
                const uint32_t bd = st + brow * 128 + ((bch ^ (brow & 7)) << 4);
                uint32_t kbh[4], kbl[4];
                ldm4(kbh, bd);
                ldm4(kbl, bd + 8192);
                mma16816(sacc[2*nn],   qfh[kk], &kbh[0]);
                mma16816(sacc[2*nn+1], qfh[kk], &kbh[2]);
                mma16816(sacc[2*nn],   qfh[kk], &kbl[0]);
                mma16816(sacc[2*nn+1], qfh[kk], &kbl[2]);
                mma16816(sacc[2*nn],   qfl[kk], &kbh[0]);
                mma16816(sacc[2*nn+1], qfl[kk], &kbh[2]);
            }
        }

        // mask + scale into log2 domain
        const int* mk = (const int*)(smem + AMSK + (it & 1) * 256);
        const float SC = 0.125f * L2E;
#pragma unroll
        for (int o = 0; o < 8; o++) {
            const int mv0 = mk[o * 8 + qp * 2];
            const int mv1 = mk[o * 8 + qp * 2 + 1];
            sacc[o][0] = mv0 ? sacc[o][0] * SC : -1.443e9f;
            sacc[o][2] = mv0 ? sacc[o][2] * SC : -1.443e9f;
            sacc[o][1] = mv1 ? sacc[o][1] * SC : -1.443e9f;
            sacc[o][3] = mv1 ? sacc[o][3] * SC : -1.443e9f;
        }

        // online softmax (rows g and g+8; 4 lanes per row share via xor 1,2)
        float mx0 = -1e30f, mx1 = -1e30f;
#pragma unroll
        for (int o = 0; o < 8; o++) {
            mx0 = fmaxf(mx0, fmaxf(sacc[o][0], sacc[o][1]));
            mx1 = fmaxf(mx1, fmaxf(sacc[o][2], sacc[o][3]));
        }
        mx0 = fmaxf(mx0, __shfl_xor_sync(0xffffffffu, mx0, 1));
        mx0 = fmaxf(mx0, __shfl_xor_sync(0xffffffffu, mx0, 2));
        mx1 = fmaxf(mx1, __shfl_xor_sync(0xffffffffu, mx1, 1));
        mx1 = fmaxf(mx1, __shfl_xor_sync(0xffffffffu, mx1, 2));
        const float mn0 = fmaxf(m2[0], mx0);
        const float mn1 = fmaxf(m2[1], mx1);
        const float al0 = ex2(m2[0] - mn0);
        const float al1 = ex2(m2[1] - mn1);
        m2[0] = mn0; m2[1] = mn1;

        float rs0 = 0.f, rs1 = 0.f;
        uint32_t pf[4][4];
#pragma unroll
        for (int o = 0; o < 8; o++) {
            const float p0 = ex2(sacc[o][0] - mn0);
            const float p1 = ex2(sacc[o][1] - mn0);
            const float p2 = ex2(sacc[o][2] - mn1);
            const float p3 = ex2(sacc[o][3] - mn1);
            rs0 += p0 + p1;
            rs1 += p2 + p3;
            const int kk = o >> 1, hf = o & 1;
            const __nv_bfloat162 pa = __floats2bfloat162_rn(p0, p1);
            const __nv_bfloat162 pb = __floats2bfloat162_rn(p2, p3);
            pf[kk][hf * 2]     = *(const uint32_t*)&pa;
            pf[kk][hf * 2 + 1] = *(const uint32_t*)&pb;
        }
        rs0 += __shfl_xor_sync(0xffffffffu, rs0, 1);
        rs0 += __shfl_xor_sync(0xffffffffu, rs0, 2);
        rs1 += __shfl_xor_sync(0xffffffffu, rs1, 1);
        rs1 += __shfl_xor_sync(0xffffffffu, rs1, 2);
        lsum[0] = lsum[0] * al0 + rs0;
        lsum[1] = lsum[1] * al1 + rs1;
#pragma unroll
        for (int o = 0; o < 8; o++) {
            accv[o][0] *= al0; accv[o][1] *= al0;
            accv[o][2] *= al1; accv[o][3] *= al1;
        }

        // O += P V   (V via ldmatrix.trans: [k][d] tile -> B frags over n=d)
#pragma unroll
        for (int nn = 0; nn < 4; nn++) {
#pragma unroll
            for (int kk = 0; kk < 4; kk++) {
                const int krow = kk * 16 + (grp & 1) * 8 + lr;
                const int ch   = nn * 2 + (grp >> 1);
                const uint32_t vd = st + 16384 + krow * 128 + ((ch ^ (krow & 7)) << 4);
                uint32_t vb[4];
                ldm4t(vb, vd);
                mma16816(accv[2*nn],   pf[kk], &vb[0]);
                mma16816(accv[2*nn+1], pf[kk], &vb[2]);
            }
        }

        __syncthreads();
        if (it + 2 < NKT) load_tile(it + 2);
    }

    // epilogue: ctx/l -> xh/xl split, merged (B,S,D) layout
    const float inv0 = 1.f / lsum[0];
    const float inv1 = 1.f / lsum[1];
    const int qr0 = q0 + wid * 16 + g;
#pragma unroll
    for (int o = 0; o < 8; o++) {
        const int d = o * 8 + qp * 2;
#pragma unroll
        for (int hr = 0; hr < 2; hr++) {
            const float v0 = accv[o][hr * 2]     * (hr ? inv1 : inv0);
            const float v1 = accv[o][hr * 2 + 1] * (hr ? inv1 : inv0);
            const size_t adr = ((size_t)(b * Ss + qr0 + hr * 8)) * Dd + h * DHd + d;
            __nv_bfloat16 h0 = __float2bfloat16(v0);
            __nv_bfloat16 h1 = __float2bfloat16(v1);
            *(__nv_bfloat162*)(oxh + adr) = __nv_bfloat162(h0, h1);
            __nv_bfloat16 l0 = __float2bfloat16(v0 - __bfloat162float(h0));
            __nv_bfloat16 l1 = __float2bfloat16(v1 - __bfloat162float(h1));
            *(__nv_bfloat162*)(oxl + adr) = __nv_bfloat162(l0, l1);
        }
    }
}

// ---------------------------------------------------------------------------
// LayerNorm
// ---------------------------------------------------------------------------
__global__ void __launch_bounds__(256)
ln1024(float* __restrict__ x, const float* __restrict__ gamma, const float* __restrict__ beta)
{
    __shared__ float red[16];
    const int row = blockIdx.x, t = threadIdx.x;
    float* xr = x + (size_t)row * Dd;
    const float4 v = *(const float4*)(xr + t*4);
    float s  = v.x + v.y + v.z + v.w;
    float s2 = v.x*v.x + v.y*v.y + v.z*v.z + v.w*v.w;
#pragma unroll
    for (int off = 16; off >= 1; off >>= 1) {
        s  += __shfl_xor_sync(0xffffffffu, s,  off);
        s2 += __shfl_xor_sync(0xffffffffu, s2, off);
    }
    if ((t & 31) == 0) { red[t>>5] = s; red[8 + (t>>5)] = s2; }
    __syncthreads();
    if (t == 0) {
        float a = 0.f, c = 0.f;
#pragma unroll
        for (int w = 0; w < 8; w++) { a += red[w]; c += red[8+w]; }
        red[0] = a; red[8] = c;
    }
    __syncthreads();
    const float mean = red[0] * (1.f/Dd);
    const float var  = red[8] * (1.f/Dd) - mean*mean;
    const float rstd = rsqrtf(var + 1e-5f);
    const float4 g  = *(const float4*)(gamma + t*4);
    const float4 be = *(const float4*)(beta  + t*4);
    float4 o;
    o.x = (v.x - mean)*rstd*g.x + be.x;
    o.y = (v.y - mean)*rstd*g.y + be.y;
    o.z = (v.z - mean)*rstd*g.z + be.z;
    o.w = (v.w - mean)*rstd*g.w + be.w;
    *(float4*)(xr + t*4) = o;
}

// ---------------------------------------------------------------------------
extern "C" void kernel_launch(void* const* d_in, const int* in_sizes, int n_in,
                              void* d_out, int out_size)
{
    const float* Q    = (const float*)d_in[0];
    const float* K    = (const float*)d_in[1];
    const float* V    = (const float*)d_in[2];
    const int*   mask = (const int*)  d_in[3];
    const float* Wq   = (const float*)d_in[4];
    const float* bq   = (const float*)d_in[5];
    const float* Wk   = (const float*)d_in[6];
    const float* bk   = (const float*)d_in[7];
    const float* Wv   = (const float*)d_in[8];
    const float* bv   = (const float*)d_in[9];
    const float* Wo   = (const float*)d_in[10];
    const float* bo   = (const float*)d_in[11];
    const float* gam  = (const float*)d_in[12];
    const float* bet  = (const float*)d_in[13];
    float* out = (float*)d_out;

    __nv_bfloat16 *xh, *xl, *wh, *wl, *qh, *ql, *kh, *kl, *vh;
    cudaGetSymbolAddress((void**)&xh, g_xh);
    cudaGetSymbolAddress((void**)&xl, g_xl);
    cudaGetSymbolAddress((void**)&wh, g_wh);
    cudaGetSymbolAddress((void**)&wl, g_wl);
    cudaGetSymbolAddress((void**)&qh, g_qh);
    cudaGetSymbolAddress((void**)&ql, g_ql);
    cudaGetSymbolAddress((void**)&kh, g_kh);
    cudaGetSymbolAddress((void**)&kl, g_kl);
    cudaGetSymbolAddress((void**)&vh, g_vh);

    cudaFuncSetAttribute(mmagemm<0>, cudaFuncAttributeMaxDynamicSharedMemorySize, GSMEM);
    cudaFuncSetAttribute(mmagemm<1>, cudaFuncAttributeMaxDynamicSharedMemorySize, GSMEM);
    cudaFuncSetAttribute(mmagemm<2>, cudaFuncAttributeMaxDynamicSharedMemorySize, GSMEM);
    cudaFuncSetAttribute(attn_mma,   cudaFuncAttributeMaxDynamicSharedMemorySize, ASMEM);

    const int W4 = Dd*Dd/4;
    const int X4 = Mm*Dd/4;
    const size_t WN = (size_t)Dd*Dd;
    cvt_split<<<(W4+255)/256, 256>>>(Wq, wh + 0*WN, wl + 0*WN, W4);
    cvt_split<<<(W4+255)/256, 256>>>(Wk, wh + 1*WN, wl + 1*WN, W4);
    cvt_split<<<(W4+255)/256, 256>>>(Wv, wh + 2*WN, wl + 2*WN, W4);
    cvt_split<<<(W4+255)/256, 256>>>(Wo, wh + 3*WN, wl + 3*WN, W4);

    const dim3 gg(Dd/128, Mm/128);          // (8, 64)

    cvt_split<<<(X4+255)/256, 256>>>(Q, xh, xl, X4);
    mmagemm<0><<<gg, 256, GSMEM>>>(xh, xl, wh + 0*WN, wl + 0*WN, bq, nullptr, nullptr, qh, ql);
    cvt_split<<<(X4+255)/256, 256>>>(K, xh, xl, X4);
    mmagemm<0><<<gg, 256, GSMEM>>>(xh, xl, wh + 1*WN, wl + 1*WN, bk, nullptr, nullptr, kh, kl);
    cvt_split<<<(X4+255)/256, 256>>>(V, xh, xl, X4);
    mmagemm<2><<<gg, 256, GSMEM>>>(xh, xl, wh + 2*WN, wl + 2*WN, bv, nullptr, nullptr, vh, nullptr);

    attn_mma<<<dim3(Ss/128, Bb*Hh), 256, ASMEM>>>(mask, xh, xl);

    mmagemm<1><<<gg, 256, GSMEM>>>(xh, xl, wh + 3*WN, wl + 3*WN, bo, Q, out, nullptr, nullptr);
    ln1024<<<Mm, 256>>>(out, gam, bet);
}